// round 6
// baseline (speedup 1.0000x reference)
#include <cuda_runtime.h>
#include <cuda_bf16.h>
#include <mma.h>
#include <cstdint>
#include <math.h>

using namespace nvcuda;
using u32 = unsigned int;

// ---------------- problem constants ----------------
#define Bc     4
#define Mc     50000
#define FINc   128
#define FOUTc  128
#define Kc     4
#define Ecap   800000
#define Dc     512
#define TOTROWS (Bc*Mc)

// ---------------- device scratch ----------------
__device__ float g_X[Kc][Mc * Dc];          // Chebyshev stack [m][b][f]; slot 0 unused
__device__ __nv_bfloat16 g_Wh[512 * 128];   // W hi  [k][n], k = kcheb*128+f
__device__ __nv_bfloat16 g_Wl[512 * 128];   // W lo  [k][n]
__device__ int   g_rowptr[Mc + 1];
__device__ int   g_cursor[Mc];
__device__ int   g_blksum[256];
__device__ int   g_col[Ecap];
__device__ float g_val[Ecap];
__device__ float g_ssum[Bc * FOUTc];
__device__ float g_u[Bc * FOUTc];

// ---------------- 0. zero counters ----------------
__global__ void k_zero() {
    for (int i = blockIdx.x * blockDim.x + threadIdx.x; i < Mc + Bc * FOUTc;
         i += gridDim.x * blockDim.x) {
        if (i < Mc) g_cursor[i] = 0;
        else        g_ssum[i - Mc] = 0.0f;
    }
}

// ---------------- 1. CSR build ----------------
__global__ void k_count(const int* __restrict__ rows, int E) {
    for (int e = blockIdx.x * blockDim.x + threadIdx.x; e < E;
         e += gridDim.x * blockDim.x)
        atomicAdd(&g_cursor[rows[e]], 1);
}

__global__ void k_scan1() {
    __shared__ int s[256];
    const int t = threadIdx.x;
    const int i = blockIdx.x * 256 + t;
    int v = (i < Mc) ? g_cursor[i] : 0;
    s[t] = v;
    __syncthreads();
    #pragma unroll
    for (int off = 1; off < 256; off <<= 1) {
        int a = (t >= off) ? s[t - off] : 0;
        __syncthreads();
        s[t] += a;
        __syncthreads();
    }
    if (i < Mc) g_rowptr[i] = s[t] - v;
    if (t == 255) g_blksum[blockIdx.x] = s[255];
}

__global__ void k_scan2(int nblk) {
    __shared__ int s[256];
    const int t = threadIdx.x;
    int v = (t < nblk) ? g_blksum[t] : 0;
    s[t] = v;
    __syncthreads();
    #pragma unroll
    for (int off = 1; off < 256; off <<= 1) {
        int a = (t >= off) ? s[t - off] : 0;
        __syncthreads();
        s[t] += a;
        __syncthreads();
    }
    g_blksum[t] = s[t] - v;
    if (t == 255) g_rowptr[Mc] = s[255];
}

__global__ void k_scan3() {
    const int i = blockIdx.x * 256 + threadIdx.x;
    if (i < Mc) {
        int val = g_rowptr[i] + g_blksum[blockIdx.x];
        g_rowptr[i] = val;
        g_cursor[i] = val;
    }
}

__global__ void k_scatter(const int* __restrict__ rows,
                          const int* __restrict__ cols,
                          const float* __restrict__ vals, int E) {
    for (int e = blockIdx.x * blockDim.x + threadIdx.x; e < E;
         e += gridDim.x * blockDim.x) {
        int r    = rows[e];
        int slot = atomicAdd(&g_cursor[r], 1);
        g_col[slot] = cols[e];
        g_val[slot] = vals[e];
    }
}

// ---------------- 2. split weights: W [k][n] bf16 hi/lo ----------------
__global__ void k_permW(const float* __restrict__ kern) {
    for (int i = blockIdx.x * blockDim.x + threadIdx.x; i < 512 * 128;
         i += gridDim.x * blockDim.x) {
        int k = i >> 7, n = i & 127;
        int kc = k >> 7, f = k & 127;
        float v = kern[(f * 4 + kc) * 128 + n];
        __nv_bfloat16 h = __float2bfloat16_rn(v);
        __nv_bfloat16 l = __float2bfloat16_rn(v - __bfloat162float(h));
        g_Wh[i] = h;
        g_Wl[i] = l;
    }
}

// ---------------- 3. SpMM: Xout = alpha*(L @ Xin) + beta*Xprev ----------------
// layout 0: tensor in native x order [b][m][f]  (float4 idx = (b*Mc+row)*32 + f4)
// layout 1: g_X order [m][b][f]                 (float4 idx = row*128 + t)
__global__ void k_spmm(const float* __restrict__ Xin, int lin,
                       const float* __restrict__ Xprev, int lprev,
                       float* __restrict__ Xout, float alpha, float beta) {
    const int r = blockIdx.x;
    const int t = threadIdx.x;
    const int b = t >> 5, f4 = t & 31;
    const int p0 = g_rowptr[r];
    const int p1 = g_rowptr[r + 1];
    const float4* Xi = reinterpret_cast<const float4*>(Xin);

    float4 acc = make_float4(0.f, 0.f, 0.f, 0.f);
    int p = p0;
    for (; p + 1 < p1; p += 2) {
        int   c0 = g_col[p],     c1 = g_col[p + 1];
        float v0 = g_val[p],     v1 = g_val[p + 1];
        size_t i0 = lin ? ((size_t)c0 * 128 + t) : (((size_t)b * Mc + c0) * 32 + f4);
        size_t i1 = lin ? ((size_t)c1 * 128 + t) : (((size_t)b * Mc + c1) * 32 + f4);
        float4 xa = Xi[i0];
        float4 xb = Xi[i1];
        acc.x = fmaf(v0, xa.x, fmaf(v1, xb.x, acc.x));
        acc.y = fmaf(v0, xa.y, fmaf(v1, xb.y, acc.y));
        acc.z = fmaf(v0, xa.z, fmaf(v1, xb.z, acc.z));
        acc.w = fmaf(v0, xa.w, fmaf(v1, xb.w, acc.w));
    }
    if (p < p1) {
        int   c0 = g_col[p];
        float v0 = g_val[p];
        size_t i0 = lin ? ((size_t)c0 * 128 + t) : (((size_t)b * Mc + c0) * 32 + f4);
        float4 xa = Xi[i0];
        acc.x = fmaf(v0, xa.x, acc.x);
        acc.y = fmaf(v0, xa.y, acc.y);
        acc.z = fmaf(v0, xa.z, acc.z);
        acc.w = fmaf(v0, xa.w, acc.w);
    }

    float4 o;
    if (beta != 0.0f) {
        size_t ip = lprev ? ((size_t)r * 128 + t) : (((size_t)b * Mc + r) * 32 + f4);
        float4 pv = reinterpret_cast<const float4*>(Xprev)[ip];
        o.x = fmaf(alpha, acc.x, beta * pv.x);
        o.y = fmaf(alpha, acc.y, beta * pv.y);
        o.z = fmaf(alpha, acc.z, beta * pv.z);
        o.w = fmaf(alpha, acc.w, beta * pv.w);
    } else {
        o.x = alpha * acc.x; o.y = alpha * acc.y;
        o.z = alpha * acc.z; o.w = alpha * acc.w;
    }
    reinterpret_cast<float4*>(Xout)[(size_t)r * 128 + t] = o;
}

// ---------------- 4. wmma bf16 GEMM: Y = relu(A @ W) ----------------
// CTA tile 128(M) x 128(N), K=512 in 8 chunks of 64.
// 8 warps in 4x2 grid. 3-term bf16 compensation (fp32 accumulate).
__device__ __forceinline__ u32 split2(float a, float b, u32& lo2) {
    __nv_bfloat16 ha = __float2bfloat16_rn(a), hb = __float2bfloat16_rn(b);
    __nv_bfloat16 la = __float2bfloat16_rn(a - __bfloat162float(ha));
    __nv_bfloat16 lb = __float2bfloat16_rn(b - __bfloat162float(hb));
    lo2 = ((u32)__bfloat16_as_ushort(lb) << 16) | __bfloat16_as_ushort(la);
    return ((u32)__bfloat16_as_ushort(hb) << 16) | __bfloat16_as_ushort(ha);
}

#define ALD 72     // A smem ldm (64 + 8 pad)
#define BLD 136    // B smem ldm (128 + 8 pad)
// dynamic smem layout (bf16 elements)
#define OFF_AH 0
#define OFF_AL (128 * ALD)
#define OFF_BH (2 * 128 * ALD)
#define OFF_BL (2 * 128 * ALD + 64 * BLD)
#define GSMEM_ELEMS (2 * 128 * ALD + 2 * 64 * BLD)

__global__ __launch_bounds__(256)
void k_gemm_wmma(const float* __restrict__ x, float* __restrict__ Y) {
    extern __shared__ __nv_bfloat16 dsm[];
    __nv_bfloat16* Ah = dsm + OFF_AH;
    __nv_bfloat16* Al = dsm + OFF_AL;
    __nv_bfloat16* Bh = dsm + OFF_BH;
    __nv_bfloat16* Bl = dsm + OFF_BL;
    __shared__ int2  rowB[128];          // x = base in x-layout, y = base in g_X layout (-1 invalid)
    __shared__ float stg[8][16][16];

    const int t   = threadIdx.x;
    const int wid = t >> 5, lid = t & 31;
    const int wm  = wid & 3;
    const int wn  = wid >> 2;
    const int r0  = blockIdx.x * 128;
    const bool full = (r0 + 128 <= TOTROWS);

    if (t < 128) {
        int gr = r0 + t;
        int2 rb = make_int2(-1, -1);
        if (gr < TOTROWS) {
            int b = gr / Mc; int m = gr - b * Mc;
            rb.x = (b * Mc + m) * 128;   // x native [b][m][f]
            rb.y = m * 512 + b * 128;    // g_X [m][b][f]
        }
        rowB[t] = rb;
    }
    __syncthreads();

    wmma::fragment<wmma::accumulator, 16, 16, 16, float> acc[2][4];
    #pragma unroll
    for (int mi = 0; mi < 2; ++mi)
        #pragma unroll
        for (int ni = 0; ni < 4; ++ni)
            wmma::fill_fragment(acc[mi][ni], 0.0f);

    for (int c = 0; c < 8; ++c) {        // 8 chunks of K=64
        const int kcheb = c >> 1;
        const int f0 = (c & 1) * 64;
        const float* Asrc = (kcheb == 0) ? x : g_X[kcheb];

        // stage A chunk: 128 rows x 64 cols fp32 -> bf16 hi/lo
        #pragma unroll
        for (int idx = t; idx < 2048; idx += 256) {
            int row = idx >> 4, c0 = (idx & 15) << 2;
            int2 rb = rowB[row];
            int base = (kcheb == 0) ? rb.x : rb.y;
            float4 v = make_float4(0.f, 0.f, 0.f, 0.f);
            if (rb.x >= 0)
                v = *reinterpret_cast<const float4*>(Asrc + base + f0 + c0);
            u32 lo01, lo23;
            u32 hi01 = split2(v.x, v.y, lo01);
            u32 hi23 = split2(v.z, v.w, lo23);
            *reinterpret_cast<uint2*>(Ah + row * ALD + c0) = make_uint2(hi01, hi23);
            *reinterpret_cast<uint2*>(Al + row * ALD + c0) = make_uint2(lo01, lo23);
        }
        // stage B chunk: 64 k-rows x 128 n-cols
        #pragma unroll
        for (int idx = t; idx < 1024; idx += 256) {
            int row = idx >> 4, n0 = (idx & 15) << 3;
            int go = (c * 64 + row) * 128 + n0;
            *reinterpret_cast<uint4*>(Bh + row * BLD + n0) =
                *reinterpret_cast<const uint4*>(g_Wh + go);
            *reinterpret_cast<uint4*>(Bl + row * BLD + n0) =
                *reinterpret_cast<const uint4*>(g_Wl + go);
        }
        __syncthreads();

        #pragma unroll
        for (int kk = 0; kk < 4; ++kk) {
            wmma::fragment<wmma::matrix_a, 16, 16, 16, __nv_bfloat16, wmma::row_major> ah[2], al[2];
            #pragma unroll
            for (int mi = 0; mi < 2; ++mi) {
                wmma::load_matrix_sync(ah[mi], Ah + (wm * 32 + mi * 16) * ALD + kk * 16, ALD);
                wmma::load_matrix_sync(al[mi], Al + (wm * 32 + mi * 16) * ALD + kk * 16, ALD);
            }
            #pragma unroll
            for (int ni = 0; ni < 4; ++ni) {
                wmma::fragment<wmma::matrix_b, 16, 16, 16, __nv_bfloat16, wmma::row_major> bh, bl;
                wmma::load_matrix_sync(bh, Bh + (kk * 16) * BLD + wn * 64 + ni * 16, BLD);
                wmma::load_matrix_sync(bl, Bl + (kk * 16) * BLD + wn * 64 + ni * 16, BLD);
                #pragma unroll
                for (int mi = 0; mi < 2; ++mi) {
                    wmma::mma_sync(acc[mi][ni], ah[mi], bh, acc[mi][ni]);
                    wmma::mma_sync(acc[mi][ni], ah[mi], bl, acc[mi][ni]);
                    wmma::mma_sync(acc[mi][ni], al[mi], bh, acc[mi][ni]);
                }
            }
        }
        __syncthreads();
    }

    // epilogue: ReLU + store
    #pragma unroll
    for (int mi = 0; mi < 2; ++mi)
        #pragma unroll
        for (int ni = 0; ni < 4; ++ni)
            #pragma unroll
            for (int e = 0; e < acc[mi][ni].num_elements; ++e)
                acc[mi][ni].x[e] = fmaxf(acc[mi][ni].x[e], 0.0f);

    if (full) {
        #pragma unroll
        for (int mi = 0; mi < 2; ++mi)
            #pragma unroll
            for (int ni = 0; ni < 4; ++ni) {
                int gr = r0 + wm * 32 + mi * 16;
                int gc = wn * 64 + ni * 16;
                wmma::store_matrix_sync(Y + (size_t)gr * 128 + gc,
                                        acc[mi][ni], 128, wmma::mem_row_major);
            }
    } else {
        for (int mi = 0; mi < 2; ++mi)
            for (int ni = 0; ni < 4; ++ni) {
                wmma::store_matrix_sync(&stg[wid][0][0], acc[mi][ni], 16,
                                        wmma::mem_row_major);
                __syncwarp();
                int gc = wn * 64 + ni * 16;
                #pragma unroll
                for (int e = lid; e < 256; e += 32) {
                    int rr = e >> 4, cc = e & 15;
                    int gr = r0 + wm * 32 + mi * 16 + rr;
                    if (gr < TOTROWS)
                        Y[(size_t)gr * 128 + gc + cc] = stg[wid][rr][cc];
                }
                __syncwarp();
            }
    }
}

// ---------------- 5. column sums for mean ----------------
__global__ void k_mean(const float* __restrict__ Y) {
    const int b = blockIdx.y;
    const int t = threadIdx.x;
    const int m0 = blockIdx.x * 128;
    const int m1 = min(m0 + 128, Mc);
    float acc = 0.0f;
    for (int m = m0; m < m1; ++m)
        acc += Y[((size_t)b * Mc + m) * 128 + t];
    atomicAdd(&g_ssum[b * 128 + t], acc);
}

// ---------------- 6. SE block ----------------
__global__ void k_se(const float* __restrict__ Wd, const float* __restrict__ bd,
                     const float* __restrict__ Wu, const float* __restrict__ bu) {
    __shared__ float s[Bc][128];
    __shared__ float d[Bc][16];
    const int t = threadIdx.x;
    #pragma unroll
    for (int b = 0; b < Bc; ++b)
        s[b][t] = g_ssum[b * 128 + t] * (1.0f / (float)Mc);
    __syncthreads();
    if (t < 64) {
        int b = t >> 4, j = t & 15;
        float z = bd[j];
        for (int f = 0; f < 128; ++f) z = fmaf(s[b][f], Wd[f * 16 + j], z);
        d[b][j] = z / (1.0f + expf(-z));
    }
    __syncthreads();
    #pragma unroll
    for (int b = 0; b < Bc; ++b) {
        float z = bu[t];
        for (int j = 0; j < 16; ++j) z = fmaf(d[b][j], Wu[j * 128 + t], z);
        g_u[b * 128 + t] = 1.0f / (1.0f + expf(-z));
    }
}

// ---------------- 7. gated scale ----------------
__global__ void k_scale(float* __restrict__ Y) {
    float4* Y4 = reinterpret_cast<float4*>(Y);
    const int N4 = Bc * Mc * 32;
    for (int i = blockIdx.x * blockDim.x + threadIdx.x; i < N4;
         i += gridDim.x * blockDim.x) {
        int o4 = i & 31;
        int b  = i / (Mc * 32);
        float4 u = reinterpret_cast<const float4*>(g_u)[b * 32 + o4];
        float4 v = Y4[i];
        v.x *= u.x; v.y *= u.y; v.z *= u.z; v.w *= u.w;
        Y4[i] = v;
    }
}

// ---------------- launch ----------------
extern "C" void kernel_launch(void* const* d_in, const int* in_sizes, int n_in,
                              void* d_out, int out_size) {
    const float* x      = (const float*)d_in[0];
    const float* L_vals = (const float*)d_in[1];
    const int*   L_rows = (const int*)  d_in[2];
    const int*   L_cols = (const int*)  d_in[3];
    const float* kern   = (const float*)d_in[4];
    const float* Wd     = (const float*)d_in[5];
    const float* bd     = (const float*)d_in[6];
    const float* Wu     = (const float*)d_in[7];
    const float* bu     = (const float*)d_in[8];
    float* Y = (float*)d_out;
    const int E = in_sizes[1];
    const int NSCAN = (Mc + 255) / 256;   // 196
    const int GSMEM_BYTES = GSMEM_ELEMS * 2;

    static int smem_set = 0;
    if (!smem_set) {
        cudaFuncSetAttribute(k_gemm_wmma,
                             cudaFuncAttributeMaxDynamicSharedMemorySize,
                             GSMEM_BYTES);
        smem_set = 1;
    }

    float* X1 = nullptr; cudaGetSymbolAddress((void**)&X1, g_X);
    float* Xs1 = X1 + (size_t)1 * Mc * Dc;
    float* Xs2 = X1 + (size_t)2 * Mc * Dc;
    float* Xs3 = X1 + (size_t)3 * Mc * Dc;

    k_zero   <<<256, 256>>>();
    k_count  <<<(E + 255) / 256, 256>>>(L_rows, E);
    k_scan1  <<<NSCAN, 256>>>();
    k_scan2  <<<1, 256>>>(NSCAN);
    k_scan3  <<<NSCAN, 256>>>();
    k_scatter<<<(E + 255) / 256, 256>>>(L_rows, L_cols, L_vals, E);
    k_permW  <<<128, 256>>>(kern);

    k_spmm<<<Mc, 128>>>(x,   0, nullptr, 0, Xs1, 1.0f,  0.0f);  // x1 = L x0
    k_spmm<<<Mc, 128>>>(Xs1, 1, x,       0, Xs2, 2.0f, -1.0f);  // x2 = 2 L x1 - x0
    k_spmm<<<Mc, 128>>>(Xs2, 1, Xs1,     1, Xs3, 2.0f, -1.0f);  // x3 = 2 L x2 - x1

    k_gemm_wmma<<<(TOTROWS + 127) / 128, 256, GSMEM_BYTES>>>(x, Y);
    k_mean  <<<dim3((Mc + 127) / 128, Bc), 128>>>(Y);
    k_se    <<<1, 128>>>(Wd, bd, Wu, bu);
    k_scale <<<2048, 256>>>(Y);
}

// round 7
// speedup vs baseline: 1.0278x; 1.0278x over previous
#include <cuda_runtime.h>
#include <cuda_bf16.h>
#include <mma.h>
#include <cstdint>
#include <math.h>

using namespace nvcuda;
using u32 = unsigned int;

// ---------------- problem constants ----------------
#define Bc     4
#define Mc     50000
#define FINc   128
#define FOUTc  128
#define Kc     4
#define Ecap   800000
#define Dc     512
#define TOTROWS (Bc*Mc)

// ---------------- device scratch ----------------
__device__ float g_X[Kc][Mc * Dc];          // Chebyshev stack [m][b][f]; slot 0 unused
__device__ __nv_bfloat16 g_Wh[512 * 128];   // W hi  [k][n], k = kcheb*128+f
__device__ __nv_bfloat16 g_Wl[512 * 128];   // W lo  [k][n]
__device__ int   g_rowptr[Mc + 1];
__device__ int   g_cursor[Mc];
__device__ int   g_blksum[256];
__device__ int   g_col[Ecap];
__device__ float g_val[Ecap];
__device__ float g_ssum[Bc * FOUTc];
__device__ float g_u[Bc * FOUTc];

// ---------------- 0. zero counters ----------------
__global__ void k_zero() {
    for (int i = blockIdx.x * blockDim.x + threadIdx.x; i < Mc + Bc * FOUTc;
         i += gridDim.x * blockDim.x) {
        if (i < Mc) g_cursor[i] = 0;
        else        g_ssum[i - Mc] = 0.0f;
    }
}

// ---------------- 1. CSR build ----------------
__global__ void k_count(const int* __restrict__ rows, int E) {
    for (int e = blockIdx.x * blockDim.x + threadIdx.x; e < E;
         e += gridDim.x * blockDim.x)
        atomicAdd(&g_cursor[rows[e]], 1);
}

__global__ void k_scan1() {
    __shared__ int s[256];
    const int t = threadIdx.x;
    const int i = blockIdx.x * 256 + t;
    int v = (i < Mc) ? g_cursor[i] : 0;
    s[t] = v;
    __syncthreads();
    #pragma unroll
    for (int off = 1; off < 256; off <<= 1) {
        int a = (t >= off) ? s[t - off] : 0;
        __syncthreads();
        s[t] += a;
        __syncthreads();
    }
    if (i < Mc) g_rowptr[i] = s[t] - v;
    if (t == 255) g_blksum[blockIdx.x] = s[255];
}

__global__ void k_scan2(int nblk) {
    __shared__ int s[256];
    const int t = threadIdx.x;
    int v = (t < nblk) ? g_blksum[t] : 0;
    s[t] = v;
    __syncthreads();
    #pragma unroll
    for (int off = 1; off < 256; off <<= 1) {
        int a = (t >= off) ? s[t - off] : 0;
        __syncthreads();
        s[t] += a;
        __syncthreads();
    }
    g_blksum[t] = s[t] - v;
    if (t == 255) g_rowptr[Mc] = s[255];
}

__global__ void k_scan3() {
    const int i = blockIdx.x * 256 + threadIdx.x;
    if (i < Mc) {
        int val = g_rowptr[i] + g_blksum[blockIdx.x];
        g_rowptr[i] = val;
        g_cursor[i] = val;
    }
}

__global__ void k_scatter(const int* __restrict__ rows,
                          const int* __restrict__ cols,
                          const float* __restrict__ vals, int E) {
    for (int e = blockIdx.x * blockDim.x + threadIdx.x; e < E;
         e += gridDim.x * blockDim.x) {
        int r    = rows[e];
        int slot = atomicAdd(&g_cursor[r], 1);
        g_col[slot] = cols[e];
        g_val[slot] = vals[e];
    }
}

// ---------------- 2. split weights: W [k][n] bf16 hi/lo ----------------
__global__ void k_permW(const float* __restrict__ kern) {
    for (int i = blockIdx.x * blockDim.x + threadIdx.x; i < 512 * 128;
         i += gridDim.x * blockDim.x) {
        int k = i >> 7, n = i & 127;
        int kc = k >> 7, f = k & 127;
        float v = kern[(f * 4 + kc) * 128 + n];
        __nv_bfloat16 h = __float2bfloat16_rn(v);
        __nv_bfloat16 l = __float2bfloat16_rn(v - __bfloat162float(h));
        g_Wh[i] = h;
        g_Wl[i] = l;
    }
}

// ---------------- 3. SpMM: Xout = alpha*(L @ Xin) + beta*Xprev ----------------
// layout 0: x native [b][m][f]  (float4 idx = (b*Mc+row)*32 + f4)
// layout 1: g_X order [m][b][f] (float4 idx = row*128 + t)
__global__ void k_spmm(const float* __restrict__ Xin, int lin,
                       const float* __restrict__ Xprev, int lprev,
                       float* __restrict__ Xout, float alpha, float beta) {
    const int r = blockIdx.x;
    const int t = threadIdx.x;
    const int b = t >> 5, f4 = t & 31;
    const int p0 = g_rowptr[r];
    const int p1 = g_rowptr[r + 1];
    const float4* Xi = reinterpret_cast<const float4*>(Xin);

    float4 acc = make_float4(0.f, 0.f, 0.f, 0.f);
    int p = p0;
    // unrolled by 4: prefetch col/val, 4 independent gathers in flight
    for (; p + 3 < p1; p += 4) {
        int   c0 = g_col[p],   c1 = g_col[p+1], c2 = g_col[p+2], c3 = g_col[p+3];
        float v0 = g_val[p],   v1 = g_val[p+1], v2 = g_val[p+2], v3 = g_val[p+3];
        size_t i0 = lin ? ((size_t)c0*128+t) : (((size_t)b*Mc+c0)*32+f4);
        size_t i1 = lin ? ((size_t)c1*128+t) : (((size_t)b*Mc+c1)*32+f4);
        size_t i2 = lin ? ((size_t)c2*128+t) : (((size_t)b*Mc+c2)*32+f4);
        size_t i3 = lin ? ((size_t)c3*128+t) : (((size_t)b*Mc+c3)*32+f4);
        float4 xa = Xi[i0];
        float4 xb = Xi[i1];
        float4 xc = Xi[i2];
        float4 xd = Xi[i3];
        acc.x = fmaf(v0,xa.x, fmaf(v1,xb.x, fmaf(v2,xc.x, fmaf(v3,xd.x, acc.x))));
        acc.y = fmaf(v0,xa.y, fmaf(v1,xb.y, fmaf(v2,xc.y, fmaf(v3,xd.y, acc.y))));
        acc.z = fmaf(v0,xa.z, fmaf(v1,xb.z, fmaf(v2,xc.z, fmaf(v3,xd.z, acc.z))));
        acc.w = fmaf(v0,xa.w, fmaf(v1,xb.w, fmaf(v2,xc.w, fmaf(v3,xd.w, acc.w))));
    }
    for (; p < p1; ++p) {
        int   c0 = g_col[p];
        float v0 = g_val[p];
        size_t i0 = lin ? ((size_t)c0*128+t) : (((size_t)b*Mc+c0)*32+f4);
        float4 xa = Xi[i0];
        acc.x = fmaf(v0, xa.x, acc.x);
        acc.y = fmaf(v0, xa.y, acc.y);
        acc.z = fmaf(v0, xa.z, acc.z);
        acc.w = fmaf(v0, xa.w, acc.w);
    }

    float4 o;
    if (beta != 0.0f) {
        size_t ip = lprev ? ((size_t)r*128+t) : (((size_t)b*Mc+r)*32+f4);
        float4 pv = reinterpret_cast<const float4*>(Xprev)[ip];
        o.x = fmaf(alpha, acc.x, beta * pv.x);
        o.y = fmaf(alpha, acc.y, beta * pv.y);
        o.z = fmaf(alpha, acc.z, beta * pv.z);
        o.w = fmaf(alpha, acc.w, beta * pv.w);
    } else {
        o.x = alpha * acc.x; o.y = alpha * acc.y;
        o.z = alpha * acc.z; o.w = alpha * acc.w;
    }
    reinterpret_cast<float4*>(Xout)[(size_t)r * 128 + t] = o;
}

// ---------------- 4. wmma bf16 GEMM: Y = relu(A @ W) ----------------
// CTA tile 128(M) x 128(N), K=512 in 32 chunks of 16 (round-5 shape).
// 8 warps in 4x2 grid. 3-term bf16 compensation (fp32 accumulate).
__device__ __forceinline__ u32 split2(float a, float b, u32& lo2) {
    __nv_bfloat16 ha = __float2bfloat16_rn(a), hb = __float2bfloat16_rn(b);
    __nv_bfloat16 la = __float2bfloat16_rn(a - __bfloat162float(ha));
    __nv_bfloat16 lb = __float2bfloat16_rn(b - __bfloat162float(hb));
    lo2 = ((u32)__bfloat16_as_ushort(lb) << 16) | __bfloat16_as_ushort(la);
    return ((u32)__bfloat16_as_ushort(hb) << 16) | __bfloat16_as_ushort(ha);
}

#define ALD 24     // A smem ldm (16 + 8 pad)
#define BLD 136    // B smem ldm (128 + 8 pad)

__global__ __launch_bounds__(256)
void k_gemm_wmma(const float* __restrict__ x, float* __restrict__ Y) {
    __shared__ __nv_bfloat16 Ah[128][ALD], Al[128][ALD];
    __shared__ __nv_bfloat16 Bh[16][BLD],  Bl[16][BLD];
    __shared__ int2  rowB[128];
    __shared__ float stg[8][16][16];

    const int t   = threadIdx.x;
    const int wid = t >> 5, lid = t & 31;
    const int wm  = wid & 3;
    const int wn  = wid >> 2;
    const int r0  = blockIdx.x * 128;
    const bool full = (r0 + 128 <= TOTROWS);

    if (t < 128) {
        int gr = r0 + t;
        int2 rb = make_int2(-1, -1);
        if (gr < TOTROWS) {
            int b = gr / Mc; int m = gr - b * Mc;
            rb.x = (b * Mc + m) * 128;   // x native [b][m][f]
            rb.y = m * 512 + b * 128;    // g_X [m][b][f]
        }
        rowB[t] = rb;
    }
    __syncthreads();

    wmma::fragment<wmma::accumulator, 16, 16, 16, float> acc[2][4];
    #pragma unroll
    for (int mi = 0; mi < 2; ++mi)
        #pragma unroll
        for (int ni = 0; ni < 4; ++ni)
            wmma::fill_fragment(acc[mi][ni], 0.0f);

    for (int c = 0; c < 32; ++c) {
        const int kcheb = c >> 3;
        const int f0 = (c & 7) << 4;
        const float* Asrc = (kcheb == 0) ? x : g_X[kcheb];

        // stage A chunk: 128 rows x 16 cols fp32 -> bf16 hi/lo
        #pragma unroll
        for (int idx = t; idx < 512; idx += 256) {
            int row = idx >> 2, c0 = (idx & 3) << 2;
            int2 rb = rowB[row];
            int base = (kcheb == 0) ? rb.x : rb.y;
            float4 v = make_float4(0.f, 0.f, 0.f, 0.f);
            if (rb.x >= 0)
                v = *reinterpret_cast<const float4*>(Asrc + base + f0 + c0);
            u32 lo01, lo23;
            u32 hi01 = split2(v.x, v.y, lo01);
            u32 hi23 = split2(v.z, v.w, lo23);
            *reinterpret_cast<uint2*>(&Ah[row][c0]) = make_uint2(hi01, hi23);
            *reinterpret_cast<uint2*>(&Al[row][c0]) = make_uint2(lo01, lo23);
        }
        // stage B chunk: 16 k-rows x 128 n-cols
        {
            int row = t >> 4, n0 = (t & 15) << 3;
            int go = (c * 16 + row) * 128 + n0;
            *reinterpret_cast<uint4*>(&Bh[row][n0]) =
                *reinterpret_cast<const uint4*>(g_Wh + go);
            *reinterpret_cast<uint4*>(&Bl[row][n0]) =
                *reinterpret_cast<const uint4*>(g_Wl + go);
        }
        __syncthreads();

        wmma::fragment<wmma::matrix_a, 16, 16, 16, __nv_bfloat16, wmma::row_major> ah[2], al[2];
        #pragma unroll
        for (int mi = 0; mi < 2; ++mi) {
            wmma::load_matrix_sync(ah[mi], &Ah[wm * 32 + mi * 16][0], ALD);
            wmma::load_matrix_sync(al[mi], &Al[wm * 32 + mi * 16][0], ALD);
        }
        #pragma unroll
        for (int ni = 0; ni < 4; ++ni) {
            wmma::fragment<wmma::matrix_b, 16, 16, 16, __nv_bfloat16, wmma::row_major> bh, bl;
            wmma::load_matrix_sync(bh, &Bh[0][wn * 64 + ni * 16], BLD);
            wmma::load_matrix_sync(bl, &Bl[0][wn * 64 + ni * 16], BLD);
            #pragma unroll
            for (int mi = 0; mi < 2; ++mi) {
                wmma::mma_sync(acc[mi][ni], ah[mi], bh, acc[mi][ni]);
                wmma::mma_sync(acc[mi][ni], ah[mi], bl, acc[mi][ni]);
                wmma::mma_sync(acc[mi][ni], al[mi], bh, acc[mi][ni]);
            }
        }
        __syncthreads();
    }

    // epilogue: ReLU + store
    #pragma unroll
    for (int mi = 0; mi < 2; ++mi)
        #pragma unroll
        for (int ni = 0; ni < 4; ++ni)
            #pragma unroll
            for (int e = 0; e < acc[mi][ni].num_elements; ++e)
                acc[mi][ni].x[e] = fmaxf(acc[mi][ni].x[e], 0.0f);

    if (full) {
        #pragma unroll
        for (int mi = 0; mi < 2; ++mi)
            #pragma unroll
            for (int ni = 0; ni < 4; ++ni) {
                int gr = r0 + wm * 32 + mi * 16;
                int gc = wn * 64 + ni * 16;
                wmma::store_matrix_sync(Y + (size_t)gr * 128 + gc,
                                        acc[mi][ni], 128, wmma::mem_row_major);
            }
    } else {
        for (int mi = 0; mi < 2; ++mi)
            for (int ni = 0; ni < 4; ++ni) {
                wmma::store_matrix_sync(&stg[wid][0][0], acc[mi][ni], 16,
                                        wmma::mem_row_major);
                __syncwarp();
                int gc = wn * 64 + ni * 16;
                #pragma unroll
                for (int e = lid; e < 256; e += 32) {
                    int rr = e >> 4, cc = e & 15;
                    int gr = r0 + wm * 32 + mi * 16 + rr;
                    if (gr < TOTROWS)
                        Y[(size_t)gr * 128 + gc + cc] = stg[wid][rr][cc];
                }
                __syncwarp();
            }
    }
}

// ---------------- 5. column sums for mean ----------------
__global__ void k_mean(const float* __restrict__ Y) {
    const int b = blockIdx.y;
    const int t = threadIdx.x;
    const int m0 = blockIdx.x * 128;
    const int m1 = min(m0 + 128, Mc);
    float acc = 0.0f;
    for (int m = m0; m < m1; ++m)
        acc += Y[((size_t)b * Mc + m) * 128 + t];
    atomicAdd(&g_ssum[b * 128 + t], acc);
}

// ---------------- 6. SE block ----------------
__global__ void k_se(const float* __restrict__ Wd, const float* __restrict__ bd,
                     const float* __restrict__ Wu, const float* __restrict__ bu) {
    __shared__ float s[Bc][128];
    __shared__ float d[Bc][16];
    const int t = threadIdx.x;
    #pragma unroll
    for (int b = 0; b < Bc; ++b)
        s[b][t] = g_ssum[b * 128 + t] * (1.0f / (float)Mc);
    __syncthreads();
    if (t < 64) {
        int b = t >> 4, j = t & 15;
        float z = bd[j];
        for (int f = 0; f < 128; ++f) z = fmaf(s[b][f], Wd[f * 16 + j], z);
        d[b][j] = z / (1.0f + expf(-z));
    }
    __syncthreads();
    #pragma unroll
    for (int b = 0; b < Bc; ++b) {
        float z = bu[t];
        for (int j = 0; j < 16; ++j) z = fmaf(d[b][j], Wu[j * 128 + t], z);
        g_u[b * 128 + t] = 1.0f / (1.0f + expf(-z));
    }
}

// ---------------- 7. gated scale ----------------
__global__ void k_scale(float* __restrict__ Y) {
    float4* Y4 = reinterpret_cast<float4*>(Y);
    const int N4 = Bc * Mc * 32;
    for (int i = blockIdx.x * blockDim.x + threadIdx.x; i < N4;
         i += gridDim.x * blockDim.x) {
        int o4 = i & 31;
        int b  = i / (Mc * 32);
        float4 u = reinterpret_cast<const float4*>(g_u)[b * 32 + o4];
        float4 v = Y4[i];
        v.x *= u.x; v.y *= u.y; v.z *= u.z; v.w *= u.w;
        Y4[i] = v;
    }
}

// ---------------- launch ----------------
extern "C" void kernel_launch(void* const* d_in, const int* in_sizes, int n_in,
                              void* d_out, int out_size) {
    const float* x      = (const float*)d_in[0];
    const float* L_vals = (const float*)d_in[1];
    const int*   L_rows = (const int*)  d_in[2];
    const int*   L_cols = (const int*)  d_in[3];
    const float* kern   = (const float*)d_in[4];
    const float* Wd     = (const float*)d_in[5];
    const float* bd     = (const float*)d_in[6];
    const float* Wu     = (const float*)d_in[7];
    const float* bu     = (const float*)d_in[8];
    float* Y = (float*)d_out;
    const int E = in_sizes[1];
    const int NSCAN = (Mc + 255) / 256;   // 196

    float* X1 = nullptr; cudaGetSymbolAddress((void**)&X1, g_X);
    float* Xs1 = X1 + (size_t)1 * Mc * Dc;
    float* Xs2 = X1 + (size_t)2 * Mc * Dc;
    float* Xs3 = X1 + (size_t)3 * Mc * Dc;

    k_zero   <<<256, 256>>>();
    k_count  <<<(E + 255) / 256, 256>>>(L_rows, E);
    k_scan1  <<<NSCAN, 256>>>();
    k_scan2  <<<1, 256>>>(NSCAN);
    k_scan3  <<<NSCAN, 256>>>();
    k_scatter<<<(E + 255) / 256, 256>>>(L_rows, L_cols, L_vals, E);
    k_permW  <<<128, 256>>>(kern);

    k_spmm<<<Mc, 128>>>(x,   0, nullptr, 0, Xs1, 1.0f,  0.0f);  // x1 = L x0
    k_spmm<<<Mc, 128>>>(Xs1, 1, x,       0, Xs2, 2.0f, -1.0f);  // x2 = 2 L x1 - x0
    k_spmm<<<Mc, 128>>>(Xs2, 1, Xs1,     1, Xs3, 2.0f, -1.0f);  // x3 = 2 L x2 - x1

    k_gemm_wmma<<<(TOTROWS + 127) / 128, 256>>>(x, Y);
    k_mean  <<<dim3((Mc + 127) / 128, Bc), 128>>>(Y);
    k_se    <<<1, 128>>>(Wd, bd, Wu, bu);
    k_scale <<<2048, 256>>>(Y);
}